// round 14
// baseline (speedup 1.0000x reference)
#include <cuda_runtime.h>
#include <cuda.h>
#include <cstdint>

// SliceTexture bilinear lookup, GB300 sm_103a — R14 (= R10 with output stores
// switched __stcs -> __stwt so the 272MB write stream stops evicting the
// texture from L2; TMA promotion back to the proven 128B).
// Per-point TMA box {40,2} gather; dense h-phase computes h, stores out_h and
// vnn[16], packs 1/(h+eps) into s_meta.w; phase C = 2 pts/warp, one LDS.128.

static constexpr int Wd = 1024;
static constexpr int Hd = 1024;
static constexpr int Cd = 17;

static constexpr int PTS     = 64;
static constexpr int THREADS = 256;
static constexpr int TILE_F  = 96;               // floats per slot (384B = 3*128B)
static constexpr int BOX_W   = 40;               // box cols (160B rows)
static constexpr int BOX_BYTES = BOX_W * 2 * 4;  // 320

__device__ __forceinline__ uint32_t smem_u32(const void* p) {
    uint32_t a;
    asm("{ .reg .u64 t; cvta.to.shared.u64 t, %1; cvt.u32.u64 %0, t; }" : "=r"(a) : "l"(p));
    return a;
}

__device__ __forceinline__ void mbar_wait_p0(uint32_t mbar) {
    asm volatile(
        "{\n\t.reg .pred P;\n\t"
        "W_%=: mbarrier.try_wait.parity.acquire.cta.shared::cta.b64 P, [%0], 0, 0x989680;\n\t"
        "@!P bra W_%=;\n\t}"
        :: "r"(mbar) : "memory");
}

// ---------------------------------------------------------------------------
// TMA kernel
// ---------------------------------------------------------------------------
__global__ __launch_bounds__(THREADS)
void slice_tma_kernel(const __grid_constant__ CUtensorMap tmap,
                      const float* __restrict__ uv,
                      float* __restrict__ out_values,   // [N,16]
                      float* __restrict__ out_h,        // [N,1]
                      float* __restrict__ out_vnn,      // [N,17]
                      int N)
{
    __shared__ alignas(128) float s_tile[PTS * TILE_F];   // 24576 B
    __shared__ float4 s_meta[PTS];                        // {fx, fy, bitcast(sh), r}
    __shared__ alignas(8) unsigned long long s_mbar;

    const int tid = threadIdx.x;
    const int p0  = blockIdx.x * PTS;
    const int np  = min(PTS, N - p0);
    const uint32_t mbar = smem_u32(&s_mbar);

    if (tid == 0) {
        asm volatile("mbarrier.init.shared.b64 [%0], %1;" :: "r"(mbar), "r"(PTS) : "memory");
    }
    __syncthreads();

    // ---- Phase A: setup + per-point TMA issue (threads 0..63) -------------
    if (tid < PTS) {
        if (tid < np) {
            const float2 uvv = __ldcs(reinterpret_cast<const float2*>(uv) + (p0 + tid));
            float x = uvv.x * (float)(Wd - 1);
            float y = uvv.y * (float)(Hd - 1);
            int x0 = (int)floorf(x);
            int y0 = (int)floorf(y);
            x0 = max(0, min(x0, Wd - 2));
            y0 = max(0, min(y0, Hd - 2));
            const int base = x0 * Cd;                 // element column in row y0
            const int c0   = base & ~3;               // 16B-aligned start column
            s_meta[tid] = make_float4(x - (float)x0, y - (float)y0,
                                      __int_as_float(base & 3), 0.0f);

            const uint32_t dst = smem_u32(s_tile) + tid * (TILE_F * 4);  // 384B slots
            asm volatile("mbarrier.arrive.expect_tx.shared.b64 _, [%0], %1;"
                         :: "r"(mbar), "r"(BOX_BYTES) : "memory");
            asm volatile(
                "cp.async.bulk.tensor.2d.shared::cta.global.tile.mbarrier::complete_tx::bytes "
                "[%0], [%1, {%2, %3}], [%4];"
                :: "r"(dst), "l"(&tmap), "r"(c0), "r"(y0), "r"(mbar)
                : "memory");
        } else {
            asm volatile("mbarrier.arrive.shared.b64 _, [%0];" :: "r"(mbar) : "memory");
        }
    }

    // arrive(release) above pairs with this acquire: s_meta + s_tile visible.
    mbar_wait_p0(mbar);

    // ---- Phase H: homogeneous channel for all points, dense lanes ---------
    // Slot layout: texel c of (y0,x0) at sh+c; (y0,x0+1) at sh+17+c;
    //              (y0+1,x0) at 40+sh+c; (y0+1,x0+1) at 57+sh+c.
    if (tid < np) {
        const float4 m  = s_meta[tid];
        const int    sh = __float_as_int(m.z);
        const float* st = &s_tile[tid * TILE_F] + sh;
        const float s00 = st[16], s01 = st[33];
        const float s10 = st[56], s11 = st[73];
        const float stp = s00 + (s01 - s00) * m.x;
        const float sbt = s10 + (s11 - s10) * m.x;
        const float h   = stp + (sbt - stp) * m.y;
        reinterpret_cast<float*>(&s_meta[tid])[3] = __fdividef(1.0f, h + 1e-5f);
        const size_t pt = (size_t)(p0 + tid);
        __stwt(out_h + pt, h);
        __stwt(out_vnn + pt * Cd + 16, h);
    }
    __syncthreads();                                  // publish s_meta.w

    // ---- Phase C: 2 points per warp (half-warp = 16 channels), branch-free -
    const int warp = tid >> 5;
    const int lane = tid & 31;
    const int half = lane >> 4;          // 0 = point A, 1 = point B
    const int c    = lane & 15;          // channel 0..15
    #pragma unroll
    for (int it = 0; it < PTS / 16; ++it) {           // 4 iterations
        const int p = (it * 8 + warp) * 2 + half;
        if (p < np) {
            const float4 m  = s_meta[p];              // one LDS.128: fx, fy, sh, r
            const int    sh = __float_as_int(m.z);
            const float* st = &s_tile[p * TILE_F] + sh;

            const float t00 = st[c],      t01 = st[c + 17];
            const float t10 = st[40 + c], t11 = st[57 + c];
            const float top = t00 + (t01 - t00) * m.x;
            const float bot = t10 + (t11 - t10) * m.x;
            const float v   = top + (bot - top) * m.y;

            const size_t pt = (size_t)(p0 + p);
            __stwt(out_vnn + pt * Cd + c, v);
            __stwt(out_values + pt * (Cd - 1) + c, v * m.w);
        }
    }
}

// ---------------------------------------------------------------------------
// Fallback (R3 LDG kernel, 166us known-good) — used only if encode fails
// ---------------------------------------------------------------------------
static constexpr int ROW4 = (Wd * Cd) / 4;
static constexpr int TEX4 = (Hd * Wd * Cd) / 4;
static constexpr int ST4  = 21;

__global__ __launch_bounds__(THREADS)
void slice_ldg_kernel(const float4* __restrict__ tex4,
                      const float*  __restrict__ uv,
                      float* __restrict__ out_values,
                      float* __restrict__ out_h,
                      float* __restrict__ out_vnn,
                      int N)
{
    __shared__ float4 s_tex[PTS * ST4];
    __shared__ int    s_a4[PTS];
    __shared__ float4 s_meta[PTS];

    const int tid = threadIdx.x;
    const int p0  = blockIdx.x * PTS;
    const int np  = min(PTS, N - p0);

    if (tid < np) {
        const float2 uvv = reinterpret_cast<const float2*>(uv)[p0 + tid];
        float x = uvv.x * (float)(Wd - 1);
        float y = uvv.y * (float)(Hd - 1);
        int x0 = (int)floorf(x);
        int y0 = (int)floorf(y);
        x0 = max(0, min(x0, Wd - 2));
        y0 = max(0, min(y0, Hd - 2));
        const int base = (y0 * Wd + x0) * Cd;
        s_a4[tid]   = base >> 2;
        s_meta[tid] = make_float4(x - (float)x0, y - (float)y0,
                                  __int_as_float(base & 3), 0.0f);
    }
    __syncthreads();

    #pragma unroll
    for (int k = 0; k < (PTS * 20) / THREADS; ++k) {
        const int w = tid + k * THREADS;
        const int p = w / 20;
        const int j = w - p * 20;
        if (p < np) {
            int idx4 = s_a4[p] + ((j < 10) ? j : (ROW4 - 10) + j);
            idx4 = min(idx4, TEX4 - 1);
            s_tex[p * ST4 + j] = __ldg(tex4 + idx4);
        }
    }
    __syncthreads();

    const int p = tid >> 2;
    const int q = tid & 3;
    if (p < np) {
        const float4 m  = s_meta[p];
        const float  fx = m.x, fy = m.y;
        const int    sh = __float_as_int(m.z);
        const float* st = reinterpret_cast<const float*>(&s_tex[p * ST4]) + sh;
        float h;
        {
            const float t00 = st[16], t01 = st[33];
            const float t10 = st[56], t11 = st[73];
            const float top = t00 + (t01 - t00) * fx;
            const float bot = t10 + (t11 - t10) * fx;
            h = top + (bot - top) * fy;
        }
        float v[4];
        const int cb = q * 4;
        #pragma unroll
        for (int i = 0; i < 4; ++i) {
            const int ch = cb + i;
            const float t00 = st[ch],      t01 = st[ch + Cd];
            const float t10 = st[40 + ch], t11 = st[40 + ch + Cd];
            const float top = t00 + (t01 - t00) * fx;
            const float bot = t10 + (t11 - t10) * fx;
            v[i] = top + (bot - top) * fy;
        }
        const size_t pt = (size_t)(p0 + p);
        float* vp = out_vnn + pt * Cd + cb;
        __stcs(vp + 0, v[0]); __stcs(vp + 1, v[1]);
        __stcs(vp + 2, v[2]); __stcs(vp + 3, v[3]);
        if (q == 0) { __stcs(out_vnn + pt * Cd + 16, h); __stcs(out_h + pt, h); }
        const float r = __fdividef(1.0f, h + 1e-5f);
        float4 vals = make_float4(v[0]*r, v[1]*r, v[2]*r, v[3]*r);
        __stcs(reinterpret_cast<float4*>(out_values) + (pt * 4 + q), vals);
    }
}

// ---------------------------------------------------------------------------
// Host
// ---------------------------------------------------------------------------
typedef CUresult (*PFN_TMapEncode)(CUtensorMap*, CUtensorMapDataType, cuuint32_t,
                                   void*, const cuuint64_t*, const cuuint64_t*,
                                   const cuuint32_t*, const cuuint32_t*,
                                   CUtensorMapInterleave, CUtensorMapSwizzle,
                                   CUtensorMapL2promotion, CUtensorMapFloatOOBfill);

extern "C" void kernel_launch(void* const* d_in, const int* in_sizes, int n_in,
                              void* d_out, int out_size)
{
    const float* tex = (const float*)d_in[0];     // [1024,1024,17]
    const float* uv  = (const float*)d_in[1];     // [N,2]
    const int N = in_sizes[1] / 2;

    float* out        = (float*)d_out;
    float* out_values = out;
    float* out_h      = out + (size_t)N * (Cd - 1);
    float* out_vnn    = out + (size_t)N * Cd;

    const int blocks = (N + PTS - 1) / PTS;

    void* fn = nullptr;
    cudaDriverEntryPointQueryResult qr = cudaDriverEntryPointSymbolNotFound;
    cudaError_t e = cudaGetDriverEntryPointByVersion(
        "cuTensorMapEncodeTiled", &fn, 12000, cudaEnableDefault, &qr);
    bool tma_ok = (e == cudaSuccess) && (qr == cudaDriverEntryPointSuccess) && fn;

    CUtensorMap tmap;
    if (tma_ok) {
        cuuint64_t dims[2]    = { (cuuint64_t)(Wd * Cd), (cuuint64_t)Hd };   // [17408, 1024]
        cuuint64_t strides[1] = { (cuuint64_t)(Wd * Cd) * sizeof(float) };  // 69632
        cuuint32_t box[2]     = { BOX_W, 2 };
        cuuint32_t es[2]      = { 1, 1 };
        CUresult r = ((PFN_TMapEncode)fn)(
            &tmap, CU_TENSOR_MAP_DATA_TYPE_FLOAT32, 2, (void*)tex,
            dims, strides, box, es,
            CU_TENSOR_MAP_INTERLEAVE_NONE, CU_TENSOR_MAP_SWIZZLE_NONE,
            CU_TENSOR_MAP_L2_PROMOTION_L2_128B, CU_TENSOR_MAP_FLOAT_OOB_FILL_NONE);
        tma_ok = (r == CUDA_SUCCESS);
    }

    if (tma_ok) {
        slice_tma_kernel<<<blocks, THREADS>>>(tmap, uv, out_values, out_h, out_vnn, N);
    } else {
        slice_ldg_kernel<<<blocks, THREADS>>>((const float4*)tex, uv,
                                              out_values, out_h, out_vnn, N);
    }
}

// round 15
// speedup vs baseline: 1.0187x; 1.0187x over previous
#include <cuda_runtime.h>
#include <cuda.h>
#include <cstdint>

// SliceTexture bilinear lookup, GB300 sm_103a — R15 (champion = R10, re-locked
// after R11-R14 falsified persistence, issue-trimming, promotion-256B, and
// write-through variants; __launch_bounds__ residency pin added, no-op at 26 regs).
//
// Structure: per-point TMA box {40,2} gather into 128B-aligned 384B SMEM slots
// (16B-aligned global coords via aligned-down + shift); dense h-phase computes
// the homogeneous channel, stores out_h and vnn[16], and packs 1/(h+1e-5) into
// s_meta.w; phase C = 2 points per warp (half-warp = 16 channels), one LDS.128
// for all params, coalesced __stcs outputs.

static constexpr int Wd = 1024;
static constexpr int Hd = 1024;
static constexpr int Cd = 17;

static constexpr int PTS     = 64;
static constexpr int THREADS = 256;
static constexpr int TILE_F  = 96;               // floats per slot (384B = 3*128B)
static constexpr int BOX_W   = 40;               // box cols (160B rows)
static constexpr int BOX_BYTES = BOX_W * 2 * 4;  // 320

__device__ __forceinline__ uint32_t smem_u32(const void* p) {
    uint32_t a;
    asm("{ .reg .u64 t; cvta.to.shared.u64 t, %1; cvt.u32.u64 %0, t; }" : "=r"(a) : "l"(p));
    return a;
}

__device__ __forceinline__ void mbar_wait_p0(uint32_t mbar) {
    asm volatile(
        "{\n\t.reg .pred P;\n\t"
        "W_%=: mbarrier.try_wait.parity.acquire.cta.shared::cta.b64 P, [%0], 0, 0x989680;\n\t"
        "@!P bra W_%=;\n\t}"
        :: "r"(mbar) : "memory");
}

// ---------------------------------------------------------------------------
// TMA kernel
// ---------------------------------------------------------------------------
__global__ __launch_bounds__(THREADS, 8)
void slice_tma_kernel(const __grid_constant__ CUtensorMap tmap,
                      const float* __restrict__ uv,
                      float* __restrict__ out_values,   // [N,16]
                      float* __restrict__ out_h,        // [N,1]
                      float* __restrict__ out_vnn,      // [N,17]
                      int N)
{
    __shared__ alignas(128) float s_tile[PTS * TILE_F];   // 24576 B
    __shared__ float4 s_meta[PTS];                        // {fx, fy, bitcast(sh), r}
    __shared__ alignas(8) unsigned long long s_mbar;

    const int tid = threadIdx.x;
    const int p0  = blockIdx.x * PTS;
    const int np  = min(PTS, N - p0);
    const uint32_t mbar = smem_u32(&s_mbar);

    if (tid == 0) {
        asm volatile("mbarrier.init.shared.b64 [%0], %1;" :: "r"(mbar), "r"(PTS) : "memory");
    }
    __syncthreads();

    // ---- Phase A: setup + per-point TMA issue (threads 0..63) -------------
    if (tid < PTS) {
        if (tid < np) {
            const float2 uvv = __ldcs(reinterpret_cast<const float2*>(uv) + (p0 + tid));
            float x = uvv.x * (float)(Wd - 1);
            float y = uvv.y * (float)(Hd - 1);
            int x0 = (int)floorf(x);
            int y0 = (int)floorf(y);
            x0 = max(0, min(x0, Wd - 2));
            y0 = max(0, min(y0, Hd - 2));
            const int base = x0 * Cd;                 // element column in row y0
            const int c0   = base & ~3;               // 16B-aligned start column
            s_meta[tid] = make_float4(x - (float)x0, y - (float)y0,
                                      __int_as_float(base & 3), 0.0f);

            const uint32_t dst = smem_u32(s_tile) + tid * (TILE_F * 4);  // 384B slots
            asm volatile("mbarrier.arrive.expect_tx.shared.b64 _, [%0], %1;"
                         :: "r"(mbar), "r"(BOX_BYTES) : "memory");
            asm volatile(
                "cp.async.bulk.tensor.2d.shared::cta.global.tile.mbarrier::complete_tx::bytes "
                "[%0], [%1, {%2, %3}], [%4];"
                :: "r"(dst), "l"(&tmap), "r"(c0), "r"(y0), "r"(mbar)
                : "memory");
        } else {
            asm volatile("mbarrier.arrive.shared.b64 _, [%0];" :: "r"(mbar) : "memory");
        }
    }

    // arrive(release) above pairs with this acquire: s_meta + s_tile visible.
    mbar_wait_p0(mbar);

    // ---- Phase H: homogeneous channel for all points, dense lanes ---------
    // Slot layout: texel c of (y0,x0) at sh+c; (y0,x0+1) at sh+17+c;
    //              (y0+1,x0) at 40+sh+c; (y0+1,x0+1) at 57+sh+c.
    if (tid < np) {
        const float4 m  = s_meta[tid];
        const int    sh = __float_as_int(m.z);
        const float* st = &s_tile[tid * TILE_F] + sh;
        const float s00 = st[16], s01 = st[33];
        const float s10 = st[56], s11 = st[73];
        const float stp = s00 + (s01 - s00) * m.x;
        const float sbt = s10 + (s11 - s10) * m.x;
        const float h   = stp + (sbt - stp) * m.y;
        reinterpret_cast<float*>(&s_meta[tid])[3] = __fdividef(1.0f, h + 1e-5f);
        const size_t pt = (size_t)(p0 + tid);
        __stcs(out_h + pt, h);
        __stcs(out_vnn + pt * Cd + 16, h);
    }
    __syncthreads();                                  // publish s_meta.w

    // ---- Phase C: 2 points per warp (half-warp = 16 channels), branch-free -
    const int warp = tid >> 5;
    const int lane = tid & 31;
    const int half = lane >> 4;          // 0 = point A, 1 = point B
    const int c    = lane & 15;          // channel 0..15
    #pragma unroll
    for (int it = 0; it < PTS / 16; ++it) {           // 4 iterations
        const int p = (it * 8 + warp) * 2 + half;
        if (p < np) {
            const float4 m  = s_meta[p];              // one LDS.128: fx, fy, sh, r
            const int    sh = __float_as_int(m.z);
            const float* st = &s_tile[p * TILE_F] + sh;

            const float t00 = st[c],      t01 = st[c + 17];
            const float t10 = st[40 + c], t11 = st[57 + c];
            const float top = t00 + (t01 - t00) * m.x;
            const float bot = t10 + (t11 - t10) * m.x;
            const float v   = top + (bot - top) * m.y;

            const size_t pt = (size_t)(p0 + p);
            __stcs(out_vnn + pt * Cd + c, v);
            __stcs(out_values + pt * (Cd - 1) + c, v * m.w);
        }
    }
}

// ---------------------------------------------------------------------------
// Fallback (R3 LDG kernel, 166us known-good) — used only if encode fails
// ---------------------------------------------------------------------------
static constexpr int ROW4 = (Wd * Cd) / 4;
static constexpr int TEX4 = (Hd * Wd * Cd) / 4;
static constexpr int ST4  = 21;

__global__ __launch_bounds__(THREADS)
void slice_ldg_kernel(const float4* __restrict__ tex4,
                      const float*  __restrict__ uv,
                      float* __restrict__ out_values,
                      float* __restrict__ out_h,
                      float* __restrict__ out_vnn,
                      int N)
{
    __shared__ float4 s_tex[PTS * ST4];
    __shared__ int    s_a4[PTS];
    __shared__ float4 s_meta[PTS];

    const int tid = threadIdx.x;
    const int p0  = blockIdx.x * PTS;
    const int np  = min(PTS, N - p0);

    if (tid < np) {
        const float2 uvv = reinterpret_cast<const float2*>(uv)[p0 + tid];
        float x = uvv.x * (float)(Wd - 1);
        float y = uvv.y * (float)(Hd - 1);
        int x0 = (int)floorf(x);
        int y0 = (int)floorf(y);
        x0 = max(0, min(x0, Wd - 2));
        y0 = max(0, min(y0, Hd - 2));
        const int base = (y0 * Wd + x0) * Cd;
        s_a4[tid]   = base >> 2;
        s_meta[tid] = make_float4(x - (float)x0, y - (float)y0,
                                  __int_as_float(base & 3), 0.0f);
    }
    __syncthreads();

    #pragma unroll
    for (int k = 0; k < (PTS * 20) / THREADS; ++k) {
        const int w = tid + k * THREADS;
        const int p = w / 20;
        const int j = w - p * 20;
        if (p < np) {
            int idx4 = s_a4[p] + ((j < 10) ? j : (ROW4 - 10) + j);
            idx4 = min(idx4, TEX4 - 1);
            s_tex[p * ST4 + j] = __ldg(tex4 + idx4);
        }
    }
    __syncthreads();

    const int p = tid >> 2;
    const int q = tid & 3;
    if (p < np) {
        const float4 m  = s_meta[p];
        const float  fx = m.x, fy = m.y;
        const int    sh = __float_as_int(m.z);
        const float* st = reinterpret_cast<const float*>(&s_tex[p * ST4]) + sh;
        float h;
        {
            const float t00 = st[16], t01 = st[33];
            const float t10 = st[56], t11 = st[73];
            const float top = t00 + (t01 - t00) * fx;
            const float bot = t10 + (t11 - t10) * fx;
            h = top + (bot - top) * fy;
        }
        float v[4];
        const int cb = q * 4;
        #pragma unroll
        for (int i = 0; i < 4; ++i) {
            const int ch = cb + i;
            const float t00 = st[ch],      t01 = st[ch + Cd];
            const float t10 = st[40 + ch], t11 = st[40 + ch + Cd];
            const float top = t00 + (t01 - t00) * fx;
            const float bot = t10 + (t11 - t10) * fx;
            v[i] = top + (bot - top) * fy;
        }
        const size_t pt = (size_t)(p0 + p);
        float* vp = out_vnn + pt * Cd + cb;
        __stcs(vp + 0, v[0]); __stcs(vp + 1, v[1]);
        __stcs(vp + 2, v[2]); __stcs(vp + 3, v[3]);
        if (q == 0) { __stcs(out_vnn + pt * Cd + 16, h); __stcs(out_h + pt, h); }
        const float r = __fdividef(1.0f, h + 1e-5f);
        float4 vals = make_float4(v[0]*r, v[1]*r, v[2]*r, v[3]*r);
        __stcs(reinterpret_cast<float4*>(out_values) + (pt * 4 + q), vals);
    }
}

// ---------------------------------------------------------------------------
// Host
// ---------------------------------------------------------------------------
typedef CUresult (*PFN_TMapEncode)(CUtensorMap*, CUtensorMapDataType, cuuint32_t,
                                   void*, const cuuint64_t*, const cuuint64_t*,
                                   const cuuint32_t*, const cuuint32_t*,
                                   CUtensorMapInterleave, CUtensorMapSwizzle,
                                   CUtensorMapL2promotion, CUtensorMapFloatOOBfill);

extern "C" void kernel_launch(void* const* d_in, const int* in_sizes, int n_in,
                              void* d_out, int out_size)
{
    const float* tex = (const float*)d_in[0];     // [1024,1024,17]
    const float* uv  = (const float*)d_in[1];     // [N,2]
    const int N = in_sizes[1] / 2;

    float* out        = (float*)d_out;
    float* out_values = out;
    float* out_h      = out + (size_t)N * (Cd - 1);
    float* out_vnn    = out + (size_t)N * Cd;

    const int blocks = (N + PTS - 1) / PTS;

    void* fn = nullptr;
    cudaDriverEntryPointQueryResult qr = cudaDriverEntryPointSymbolNotFound;
    cudaError_t e = cudaGetDriverEntryPointByVersion(
        "cuTensorMapEncodeTiled", &fn, 12000, cudaEnableDefault, &qr);
    bool tma_ok = (e == cudaSuccess) && (qr == cudaDriverEntryPointSuccess) && fn;

    CUtensorMap tmap;
    if (tma_ok) {
        cuuint64_t dims[2]    = { (cuuint64_t)(Wd * Cd), (cuuint64_t)Hd };   // [17408, 1024]
        cuuint64_t strides[1] = { (cuuint64_t)(Wd * Cd) * sizeof(float) };  // 69632
        cuuint32_t box[2]     = { BOX_W, 2 };
        cuuint32_t es[2]      = { 1, 1 };
        CUresult r = ((PFN_TMapEncode)fn)(
            &tmap, CU_TENSOR_MAP_DATA_TYPE_FLOAT32, 2, (void*)tex,
            dims, strides, box, es,
            CU_TENSOR_MAP_INTERLEAVE_NONE, CU_TENSOR_MAP_SWIZZLE_NONE,
            CU_TENSOR_MAP_L2_PROMOTION_L2_128B, CU_TENSOR_MAP_FLOAT_OOB_FILL_NONE);
        tma_ok = (r == CUDA_SUCCESS);
    }

    if (tma_ok) {
        slice_tma_kernel<<<blocks, THREADS>>>(tmap, uv, out_values, out_h, out_vnn, N);
    } else {
        slice_ldg_kernel<<<blocks, THREADS>>>((const float4*)tex, uv,
                                              out_values, out_h, out_vnn, N);
    }
}

// round 16
// speedup vs baseline: 1.0291x; 1.0102x over previous
#include <cuda_runtime.h>
#include <cuda.h>
#include <cstdint>

// SliceTexture bilinear lookup, GB300 sm_103a — R16 (= champion R10/R15 +
// bank-conflict fixes that don't touch TMA alignment):
//  - Phase C: half-warp B reads texel pairs in swapped order and lerps with
//    1-fx (lerp commutation) -> A/B bank windows offset by 17, conflicts ~gone.
//  - Phase H: order-independent weighted sum with lane-rotated texel order
//    -> 8-way conflicts become ~2-way.

static constexpr int Wd = 1024;
static constexpr int Hd = 1024;
static constexpr int Cd = 17;

static constexpr int PTS     = 64;
static constexpr int THREADS = 256;
static constexpr int TILE_F  = 96;               // floats per slot (384B = 3*128B)
static constexpr int BOX_W   = 40;               // box cols (160B rows)
static constexpr int BOX_BYTES = BOX_W * 2 * 4;  // 320

__device__ __forceinline__ uint32_t smem_u32(const void* p) {
    uint32_t a;
    asm("{ .reg .u64 t; cvta.to.shared.u64 t, %1; cvt.u32.u64 %0, t; }" : "=r"(a) : "l"(p));
    return a;
}

__device__ __forceinline__ void mbar_wait_p0(uint32_t mbar) {
    asm volatile(
        "{\n\t.reg .pred P;\n\t"
        "W_%=: mbarrier.try_wait.parity.acquire.cta.shared::cta.b64 P, [%0], 0, 0x989680;\n\t"
        "@!P bra W_%=;\n\t}"
        :: "r"(mbar) : "memory");
}

// ---------------------------------------------------------------------------
// TMA kernel
// ---------------------------------------------------------------------------
__global__ __launch_bounds__(THREADS, 8)
void slice_tma_kernel(const __grid_constant__ CUtensorMap tmap,
                      const float* __restrict__ uv,
                      float* __restrict__ out_values,   // [N,16]
                      float* __restrict__ out_h,        // [N,1]
                      float* __restrict__ out_vnn,      // [N,17]
                      int N)
{
    __shared__ alignas(128) float s_tile[PTS * TILE_F];   // 24576 B
    __shared__ float4 s_meta[PTS];                        // {fx, fy, bitcast(sh), r}
    __shared__ alignas(8) unsigned long long s_mbar;

    const int tid = threadIdx.x;
    const int p0  = blockIdx.x * PTS;
    const int np  = min(PTS, N - p0);
    const uint32_t mbar = smem_u32(&s_mbar);

    if (tid == 0) {
        asm volatile("mbarrier.init.shared.b64 [%0], %1;" :: "r"(mbar), "r"(PTS) : "memory");
    }
    __syncthreads();

    // ---- Phase A: setup + per-point TMA issue (threads 0..63) -------------
    if (tid < PTS) {
        if (tid < np) {
            const float2 uvv = __ldcs(reinterpret_cast<const float2*>(uv) + (p0 + tid));
            float x = uvv.x * (float)(Wd - 1);
            float y = uvv.y * (float)(Hd - 1);
            int x0 = (int)floorf(x);
            int y0 = (int)floorf(y);
            x0 = max(0, min(x0, Wd - 2));
            y0 = max(0, min(y0, Hd - 2));
            const int base = x0 * Cd;                 // element column in row y0
            const int c0   = base & ~3;               // 16B-aligned start column
            s_meta[tid] = make_float4(x - (float)x0, y - (float)y0,
                                      __int_as_float(base & 3), 0.0f);

            const uint32_t dst = smem_u32(s_tile) + tid * (TILE_F * 4);  // 384B slots
            asm volatile("mbarrier.arrive.expect_tx.shared.b64 _, [%0], %1;"
                         :: "r"(mbar), "r"(BOX_BYTES) : "memory");
            asm volatile(
                "cp.async.bulk.tensor.2d.shared::cta.global.tile.mbarrier::complete_tx::bytes "
                "[%0], [%1, {%2, %3}], [%4];"
                :: "r"(dst), "l"(&tmap), "r"(c0), "r"(y0), "r"(mbar)
                : "memory");
        } else {
            asm volatile("mbarrier.arrive.shared.b64 _, [%0];" :: "r"(mbar) : "memory");
        }
    }

    // arrive(release) above pairs with this acquire: s_meta + s_tile visible.
    mbar_wait_p0(mbar);

    // ---- Phase H: homogeneous channel, lane-rotated order-free sum --------
    // Slot layout: texel c of (y0,x0) at sh+c; (y0,x0+1) at sh+17+c;
    //              (y0+1,x0) at 40+sh+c; (y0+1,x0+1) at 57+sh+c.
    // h = sum over 4 texels of bilinear weight * value — order-independent,
    // so each lane reads texels rotated by (lane&3): 32 lanes spread over
    // 16 banks instead of 4 (kills 8-way conflicts).
    if (tid < np) {
        const float4 m  = s_meta[tid];
        const int    sh = __float_as_int(m.z);
        const float* st = &s_tile[tid * TILE_F] + sh;
        const int r0 = tid & 3;
        float h = 0.0f;
        #pragma unroll
        for (int j = 0; j < 4; ++j) {
            const int idx = (r0 + j) & 3;                        // texel id
            const int K   = (idx & 1) * 17 + (idx >> 1) * 40;    // 0,17,40,57
            const float wx = (idx & 1)  ? m.x : 1.0f - m.x;
            const float wy = (idx >> 1) ? m.y : 1.0f - m.y;
            h += (wx * wy) * st[16 + K];
        }
        reinterpret_cast<float*>(&s_meta[tid])[3] = __fdividef(1.0f, h + 1e-5f);
        const size_t pt = (size_t)(p0 + tid);
        __stcs(out_h + pt, h);
        __stcs(out_vnn + pt * Cd + 16, h);
    }
    __syncthreads();                                  // publish s_meta.w

    // ---- Phase C: 2 points per warp; B half reads pairs swapped -----------
    // lerp(t00,t01,fx) == lerp(t01,t00,1-fx): half-warp B loads the +17
    // element first and lerps with 1-fx, offsetting its bank window by 17
    // from half-warp A within every LDS instruction.
    const int warp = tid >> 5;
    const int lane = tid & 31;
    const int half = lane >> 4;          // 0 = point A, 1 = point B
    const int c    = lane & 15;          // channel 0..15
    const int oa   = half * 17;          // first-read offset within pair
    const int ob   = 17 - oa;            // second-read offset
    #pragma unroll
    for (int it = 0; it < PTS / 16; ++it) {           // 4 iterations
        const int p = (it * 8 + warp) * 2 + half;
        if (p < np) {
            const float4 m   = s_meta[p];             // one LDS.128: fx, fy, sh, r
            const int    sh  = __float_as_int(m.z);
            const float  fxx = half ? 1.0f - m.x : m.x;
            const float* st  = &s_tile[p * TILE_F] + sh;

            const float ta = st[c + oa],      tb = st[c + ob];       // top pair
            const float tc = st[40 + c + oa], td = st[40 + c + ob];  // bottom pair
            const float top = ta + (tb - ta) * fxx;
            const float bot = tc + (td - tc) * fxx;
            const float v   = top + (bot - top) * m.y;

            const size_t pt = (size_t)(p0 + p);
            __stcs(out_vnn + pt * Cd + c, v);
            __stcs(out_values + pt * (Cd - 1) + c, v * m.w);
        }
    }
}

// ---------------------------------------------------------------------------
// Fallback (R3 LDG kernel, 166us known-good) — used only if encode fails
// ---------------------------------------------------------------------------
static constexpr int ROW4 = (Wd * Cd) / 4;
static constexpr int TEX4 = (Hd * Wd * Cd) / 4;
static constexpr int ST4  = 21;

__global__ __launch_bounds__(THREADS)
void slice_ldg_kernel(const float4* __restrict__ tex4,
                      const float*  __restrict__ uv,
                      float* __restrict__ out_values,
                      float* __restrict__ out_h,
                      float* __restrict__ out_vnn,
                      int N)
{
    __shared__ float4 s_tex[PTS * ST4];
    __shared__ int    s_a4[PTS];
    __shared__ float4 s_meta[PTS];

    const int tid = threadIdx.x;
    const int p0  = blockIdx.x * PTS;
    const int np  = min(PTS, N - p0);

    if (tid < np) {
        const float2 uvv = reinterpret_cast<const float2*>(uv)[p0 + tid];
        float x = uvv.x * (float)(Wd - 1);
        float y = uvv.y * (float)(Hd - 1);
        int x0 = (int)floorf(x);
        int y0 = (int)floorf(y);
        x0 = max(0, min(x0, Wd - 2));
        y0 = max(0, min(y0, Hd - 2));
        const int base = (y0 * Wd + x0) * Cd;
        s_a4[tid]   = base >> 2;
        s_meta[tid] = make_float4(x - (float)x0, y - (float)y0,
                                  __int_as_float(base & 3), 0.0f);
    }
    __syncthreads();

    #pragma unroll
    for (int k = 0; k < (PTS * 20) / THREADS; ++k) {
        const int w = tid + k * THREADS;
        const int p = w / 20;
        const int j = w - p * 20;
        if (p < np) {
            int idx4 = s_a4[p] + ((j < 10) ? j : (ROW4 - 10) + j);
            idx4 = min(idx4, TEX4 - 1);
            s_tex[p * ST4 + j] = __ldg(tex4 + idx4);
        }
    }
    __syncthreads();

    const int p = tid >> 2;
    const int q = tid & 3;
    if (p < np) {
        const float4 m  = s_meta[p];
        const float  fx = m.x, fy = m.y;
        const int    sh = __float_as_int(m.z);
        const float* st = reinterpret_cast<const float*>(&s_tex[p * ST4]) + sh;
        float h;
        {
            const float t00 = st[16], t01 = st[33];
            const float t10 = st[56], t11 = st[73];
            const float top = t00 + (t01 - t00) * fx;
            const float bot = t10 + (t11 - t10) * fx;
            h = top + (bot - top) * fy;
        }
        float v[4];
        const int cb = q * 4;
        #pragma unroll
        for (int i = 0; i < 4; ++i) {
            const int ch = cb + i;
            const float t00 = st[ch],      t01 = st[ch + Cd];
            const float t10 = st[40 + ch], t11 = st[40 + ch + Cd];
            const float top = t00 + (t01 - t00) * fx;
            const float bot = t10 + (t11 - t10) * fx;
            v[i] = top + (bot - top) * fy;
        }
        const size_t pt = (size_t)(p0 + p);
        float* vp = out_vnn + pt * Cd + cb;
        __stcs(vp + 0, v[0]); __stcs(vp + 1, v[1]);
        __stcs(vp + 2, v[2]); __stcs(vp + 3, v[3]);
        if (q == 0) { __stcs(out_vnn + pt * Cd + 16, h); __stcs(out_h + pt, h); }
        const float r = __fdividef(1.0f, h + 1e-5f);
        float4 vals = make_float4(v[0]*r, v[1]*r, v[2]*r, v[3]*r);
        __stcs(reinterpret_cast<float4*>(out_values) + (pt * 4 + q), vals);
    }
}

// ---------------------------------------------------------------------------
// Host
// ---------------------------------------------------------------------------
typedef CUresult (*PFN_TMapEncode)(CUtensorMap*, CUtensorMapDataType, cuuint32_t,
                                   void*, const cuuint64_t*, const cuuint64_t*,
                                   const cuuint32_t*, const cuuint32_t*,
                                   CUtensorMapInterleave, CUtensorMapSwizzle,
                                   CUtensorMapL2promotion, CUtensorMapFloatOOBfill);

extern "C" void kernel_launch(void* const* d_in, const int* in_sizes, int n_in,
                              void* d_out, int out_size)
{
    const float* tex = (const float*)d_in[0];     // [1024,1024,17]
    const float* uv  = (const float*)d_in[1];     // [N,2]
    const int N = in_sizes[1] / 2;

    float* out        = (float*)d_out;
    float* out_values = out;
    float* out_h      = out + (size_t)N * (Cd - 1);
    float* out_vnn    = out + (size_t)N * Cd;

    const int blocks = (N + PTS - 1) / PTS;

    void* fn = nullptr;
    cudaDriverEntryPointQueryResult qr = cudaDriverEntryPointSymbolNotFound;
    cudaError_t e = cudaGetDriverEntryPointByVersion(
        "cuTensorMapEncodeTiled", &fn, 12000, cudaEnableDefault, &qr);
    bool tma_ok = (e == cudaSuccess) && (qr == cudaDriverEntryPointSuccess) && fn;

    CUtensorMap tmap;
    if (tma_ok) {
        cuuint64_t dims[2]    = { (cuuint64_t)(Wd * Cd), (cuuint64_t)Hd };   // [17408, 1024]
        cuuint64_t strides[1] = { (cuuint64_t)(Wd * Cd) * sizeof(float) };  // 69632
        cuuint32_t box[2]     = { BOX_W, 2 };
        cuuint32_t es[2]      = { 1, 1 };
        CUresult r = ((PFN_TMapEncode)fn)(
            &tmap, CU_TENSOR_MAP_DATA_TYPE_FLOAT32, 2, (void*)tex,
            dims, strides, box, es,
            CU_TENSOR_MAP_INTERLEAVE_NONE, CU_TENSOR_MAP_SWIZZLE_NONE,
            CU_TENSOR_MAP_L2_PROMOTION_L2_128B, CU_TENSOR_MAP_FLOAT_OOB_FILL_NONE);
        tma_ok = (r == CUDA_SUCCESS);
    }

    if (tma_ok) {
        slice_tma_kernel<<<blocks, THREADS>>>(tmap, uv, out_values, out_h, out_vnn, N);
    } else {
        slice_ldg_kernel<<<blocks, THREADS>>>((const float4*)tex, uv,
                                              out_values, out_h, out_vnn, N);
    }
}